// round 1
// baseline (speedup 1.0000x reference)
#include <cuda_runtime.h>
#include <math.h>

// Problem constants
#define BATCH   2
#define SEQ     2048
#define DMODEL  1024
#define NHEADS  16
#define DHEAD   64
#define MROWS   (BATCH * SEQ)     // 4096 tokens

// Scratch (device globals — allocation-free)
__device__ float g_q[MROWS * DMODEL];
__device__ float g_k[MROWS * DMODEL];
__device__ float g_v[MROWS * DMODEL];
__device__ float g_att[MROWS * DMODEL];

// ---------------------------------------------------------------------------
// Generic 128x128x16 SGEMM body:  C = A @ W^T + bias
// A: [4096,1024] row-major, W: [1024,1024] row-major (so W^T columns are W rows)
// block: 256 threads, each computes 8x8.
// ---------------------------------------------------------------------------
__device__ __forceinline__ void gemm_body(const float* __restrict__ A,
                                          const float* __restrict__ W,
                                          const float* __restrict__ bias,
                                          float* __restrict__ C)
{
    __shared__ float As[16][128];
    __shared__ float Bs[16][128];

    const int tid = threadIdx.x;
    const int bm = blockIdx.y;          // 0..31 (rows of A, 128 each)
    const int bn = blockIdx.x;          // 0..7  (rows of W = cols of C, 128 each)

    const int lrow = tid >> 1;          // 0..127
    const int lk   = (tid & 1) << 3;    // 0 or 8

    const float* Ag = A + (size_t)(bm * 128 + lrow) * DMODEL + lk;
    const float* Wg = W + (size_t)(bn * 128 + lrow) * DMODEL + lk;

    const int ty = tid >> 4;            // 0..15
    const int tx = tid & 15;            // 0..15
    const int r0 = ty << 3;
    const int c0 = tx << 3;

    float acc[8][8] = {};

    for (int k0 = 0; k0 < DMODEL; k0 += 16) {
        float4 a0 = *(const float4*)(Ag + k0);
        float4 a1 = *(const float4*)(Ag + k0 + 4);
        float4 b0 = *(const float4*)(Wg + k0);
        float4 b1 = *(const float4*)(Wg + k0 + 4);

        As[lk + 0][lrow] = a0.x; As[lk + 1][lrow] = a0.y;
        As[lk + 2][lrow] = a0.z; As[lk + 3][lrow] = a0.w;
        As[lk + 4][lrow] = a1.x; As[lk + 5][lrow] = a1.y;
        As[lk + 6][lrow] = a1.z; As[lk + 7][lrow] = a1.w;

        Bs[lk + 0][lrow] = b0.x; Bs[lk + 1][lrow] = b0.y;
        Bs[lk + 2][lrow] = b0.z; Bs[lk + 3][lrow] = b0.w;
        Bs[lk + 4][lrow] = b1.x; Bs[lk + 5][lrow] = b1.y;
        Bs[lk + 6][lrow] = b1.z; Bs[lk + 7][lrow] = b1.w;

        __syncthreads();

        #pragma unroll
        for (int kk = 0; kk < 16; ++kk) {
            float a[8], b[8];
            *(float4*)&a[0] = *(const float4*)&As[kk][r0];
            *(float4*)&a[4] = *(const float4*)&As[kk][r0 + 4];
            *(float4*)&b[0] = *(const float4*)&Bs[kk][c0];
            *(float4*)&b[4] = *(const float4*)&Bs[kk][c0 + 4];
            #pragma unroll
            for (int i = 0; i < 8; ++i)
                #pragma unroll
                for (int j = 0; j < 8; ++j)
                    acc[i][j] += a[i] * b[j];
        }
        __syncthreads();
    }

    const int gr = bm * 128 + r0;
    const int gc = bn * 128 + c0;
    float4 bb0 = *(const float4*)(bias + gc);
    float4 bb1 = *(const float4*)(bias + gc + 4);

    #pragma unroll
    for (int i = 0; i < 8; ++i) {
        float4 o0, o1;
        o0.x = acc[i][0] + bb0.x; o0.y = acc[i][1] + bb0.y;
        o0.z = acc[i][2] + bb0.z; o0.w = acc[i][3] + bb0.w;
        o1.x = acc[i][4] + bb1.x; o1.y = acc[i][5] + bb1.y;
        o1.z = acc[i][6] + bb1.z; o1.w = acc[i][7] + bb1.w;
        float* Cp = C + (size_t)(gr + i) * DMODEL + gc;
        *(float4*)(Cp)     = o0;
        *(float4*)(Cp + 4) = o1;
    }
}

__global__ __launch_bounds__(256, 2)
void gemm_qkv_kernel(const float* __restrict__ x,
                     const float* __restrict__ wq, const float* __restrict__ bq,
                     const float* __restrict__ wk, const float* __restrict__ bk,
                     const float* __restrict__ wv, const float* __restrict__ bv)
{
    const float* W; const float* bias; float* C;
    if (blockIdx.z == 0)      { W = wq; bias = bq; C = g_q; }
    else if (blockIdx.z == 1) { W = wk; bias = bk; C = g_k; }
    else                      { W = wv; bias = bv; C = g_v; }
    gemm_body(x, W, bias, C);
}

__global__ __launch_bounds__(256, 2)
void gemm_out_kernel(const float* __restrict__ wo, const float* __restrict__ bo,
                     float* __restrict__ out)
{
    gemm_body(g_att, wo, bo, out);
}

// ---------------------------------------------------------------------------
// Flash attention (causal + key padding mask), fp32.
// One block = 64 q-rows of one (b,h). 256 threads, each a 4x4 micro-tile.
// smem: Qt (d-major), KP (K d-major, reused as P row-major), Vs (row-major).
// ---------------------------------------------------------------------------
__global__ __launch_bounds__(256)
void attn_kernel(const unsigned char* __restrict__ mask)
{
    __shared__ float Qt[64][64];   // Qt[d][r]
    __shared__ float KP[64][64];   // Kt[d][c]  then  P[r][c]
    __shared__ float Vs[64][64];   // Vs[c][d]

    const int tid = threadIdx.x;
    const int qt  = blockIdx.x;            // q tile (0..31)
    const int bh  = blockIdx.y;            // b*16 + h
    const int b   = bh >> 4;
    const int h   = bh & 15;

    const int ty = tid >> 4, tx = tid & 15;
    const int r0 = ty << 2, c0 = tx << 2;

    const size_t headoff = (size_t)h * DHEAD;
    const float* Qg = g_q + ((size_t)(b * SEQ + qt * 64)) * DMODEL + headoff;
    const unsigned char* mb = mask + (size_t)b * SEQ;

    // load Q tile transposed (d-major)
    {
        const int lr = tid >> 4;           // 0..15
        const int ld = (tid & 15) << 2;    // 0..60
        #pragma unroll
        for (int it = 0; it < 4; ++it) {
            int r = lr + it * 16;
            float4 v = *(const float4*)(Qg + (size_t)r * DMODEL + ld);
            Qt[ld + 0][r] = v.x; Qt[ld + 1][r] = v.y;
            Qt[ld + 2][r] = v.z; Qt[ld + 3][r] = v.w;
        }
    }

    float mrow[4], lsum[4], acc[4][4];
    #pragma unroll
    for (int i = 0; i < 4; ++i) {
        mrow[i] = -1e30f; lsum[i] = 0.f;
        #pragma unroll
        for (int j = 0; j < 4; ++j) acc[i][j] = 0.f;
    }

    for (int j = 0; j <= qt; ++j) {
        __syncthreads();   // prior iteration's Vs / P reads complete

        // load K (transposed) and V (row-major)
        const float* Kg = g_k + ((size_t)(b * SEQ + j * 64)) * DMODEL + headoff;
        const float* Vg = g_v + ((size_t)(b * SEQ + j * 64)) * DMODEL + headoff;
        {
            const int lr = tid >> 4;
            const int ld = (tid & 15) << 2;
            #pragma unroll
            for (int it = 0; it < 4; ++it) {
                int r = lr + it * 16;
                float4 kv = *(const float4*)(Kg + (size_t)r * DMODEL + ld);
                KP[ld + 0][r] = kv.x; KP[ld + 1][r] = kv.y;
                KP[ld + 2][r] = kv.z; KP[ld + 3][r] = kv.w;
                float4 vv = *(const float4*)(Vg + (size_t)r * DMODEL + ld);
                *(float4*)&Vs[r][ld] = vv;
            }
        }
        __syncthreads();

        // S = Q K^T for my 4x4
        float s[4][4] = {};
        #pragma unroll 16
        for (int kk = 0; kk < 64; ++kk) {
            float4 av = *(const float4*)&Qt[kk][r0];
            float4 bv = *(const float4*)&KP[kk][c0];
            float a[4] = {av.x, av.y, av.z, av.w};
            float bb[4] = {bv.x, bv.y, bv.z, bv.w};
            #pragma unroll
            for (int i = 0; i < 4; ++i)
                #pragma unroll
                for (int jj = 0; jj < 4; ++jj)
                    s[i][jj] += a[i] * bb[jj];
        }

        // scale + mask (causal + key padding)
        const int qbase = qt * 64 + r0;
        const int kbase = j * 64 + c0;
        uchar4 m4 = *(const uchar4*)(mb + kbase);
        unsigned char mk[4] = {m4.x, m4.y, m4.z, m4.w};
        #pragma unroll
        for (int i = 0; i < 4; ++i)
            #pragma unroll
            for (int jj = 0; jj < 4; ++jj) {
                float v = s[i][jj] * 0.125f;   // 1/sqrt(64)
                if ((kbase + jj > qbase + i) || mk[jj]) v = -1e30f;
                s[i][jj] = v;
            }

        __syncthreads();   // everyone done reading Kt before P overwrites it

        // online softmax update
        #pragma unroll
        for (int i = 0; i < 4; ++i) {
            float tm = fmaxf(fmaxf(s[i][0], s[i][1]), fmaxf(s[i][2], s[i][3]));
            tm = fmaxf(tm, __shfl_xor_sync(0xffffffffu, tm, 8));
            tm = fmaxf(tm, __shfl_xor_sync(0xffffffffu, tm, 4));
            tm = fmaxf(tm, __shfl_xor_sync(0xffffffffu, tm, 2));
            tm = fmaxf(tm, __shfl_xor_sync(0xffffffffu, tm, 1));
            float mn = fmaxf(mrow[i], tm);
            mn = fmaxf(mn, -1e29f);            // safety for all-masked tiles
            float al = __expf(mrow[i] - mn);
            mrow[i] = mn;
            float ps = 0.f;
            #pragma unroll
            for (int jj = 0; jj < 4; ++jj) {
                float p = __expf(s[i][jj] - mn);
                s[i][jj] = p;
                ps += p;
            }
            ps += __shfl_xor_sync(0xffffffffu, ps, 8);
            ps += __shfl_xor_sync(0xffffffffu, ps, 4);
            ps += __shfl_xor_sync(0xffffffffu, ps, 2);
            ps += __shfl_xor_sync(0xffffffffu, ps, 1);
            lsum[i] = lsum[i] * al + ps;
            #pragma unroll
            for (int jj = 0; jj < 4; ++jj) acc[i][jj] *= al;
        }

        // write P row-major into KP
        #pragma unroll
        for (int i = 0; i < 4; ++i)
            #pragma unroll
            for (int jj = 0; jj < 4; ++jj)
                KP[r0 + i][c0 + jj] = s[i][jj];

        __syncthreads();

        // O += P @ V
        #pragma unroll 16
        for (int kk = 0; kk < 64; ++kk) {
            float4 bv = *(const float4*)&Vs[kk][c0];
            float bb[4] = {bv.x, bv.y, bv.z, bv.w};
            #pragma unroll
            for (int i = 0; i < 4; ++i) {
                float a = KP[r0 + i][kk];
                #pragma unroll
                for (int jj = 0; jj < 4; ++jj)
                    acc[i][jj] += a * bb[jj];
            }
        }
    }

    // normalize and write out
    float* Og = g_att + ((size_t)(b * SEQ + qt * 64)) * DMODEL + headoff;
    #pragma unroll
    for (int i = 0; i < 4; ++i) {
        float inv = 1.0f / lsum[i];
        float4 o;
        o.x = acc[i][0] * inv; o.y = acc[i][1] * inv;
        o.z = acc[i][2] * inv; o.w = acc[i][3] * inv;
        *(float4*)(Og + (size_t)(r0 + i) * DMODEL + c0) = o;
    }
}

// ---------------------------------------------------------------------------
extern "C" void kernel_launch(void* const* d_in, const int* in_sizes, int n_in,
                              void* d_out, int out_size)
{
    const float*         x    = (const float*)d_in[0];
    const unsigned char* mask = (const unsigned char*)d_in[1];
    const float*         wq   = (const float*)d_in[2];
    const float*         bq   = (const float*)d_in[3];
    const float*         wk   = (const float*)d_in[4];
    const float*         bk   = (const float*)d_in[5];
    const float*         wv   = (const float*)d_in[6];
    const float*         bv   = (const float*)d_in[7];
    const float*         wo   = (const float*)d_in[8];
    const float*         bo   = (const float*)d_in[9];
    float*               out  = (float*)d_out;

    dim3 blk(256);
    // QKV projections: grid (N/128, M/128, 3)
    gemm_qkv_kernel<<<dim3(DMODEL / 128, MROWS / 128, 3), blk>>>(
        x, wq, bq, wk, bk, wv, bv);
    // attention: (32 q-tiles, 32 b*h)
    attn_kernel<<<dim3(SEQ / 64, BATCH * NHEADS), blk>>>(mask);
    // output projection
    gemm_out_kernel<<<dim3(DMODEL / 128, MROWS / 128), blk>>>(wo, bo, out);
}

// round 3
// speedup vs baseline: 2.4858x; 2.4858x over previous
#include <cuda_runtime.h>
#include <cuda_bf16.h>
#include <stdint.h>
#include <math.h>

// Problem constants
#define BATCH   2
#define SEQ     2048
#define DMODEL  1024
#define NHEADS  16
#define DHEAD   64
#define MROWS   (BATCH * SEQ)     // 4096 tokens

// ---------------------------------------------------------------------------
// Device-global scratch (allocation-free)
// ---------------------------------------------------------------------------
__device__ float g_q[MROWS * DMODEL];
__device__ float g_k[MROWS * DMODEL];
__device__ float g_v[MROWS * DMODEL];
__device__ float g_att[MROWS * DMODEL];

__device__ __nv_bfloat16 g_xhi[MROWS * DMODEL];
__device__ __nv_bfloat16 g_xlo[MROWS * DMODEL];
__device__ __nv_bfloat16 g_ahi[MROWS * DMODEL];
__device__ __nv_bfloat16 g_alo[MROWS * DMODEL];
__device__ __nv_bfloat16 g_whi[4][DMODEL * DMODEL];
__device__ __nv_bfloat16 g_wlo[4][DMODEL * DMODEL];

// ---------------------------------------------------------------------------
// warp-mma helpers (plain sm_80-class PTX; compiles at compute_103)
// ---------------------------------------------------------------------------
__device__ __forceinline__ uint32_t smem_u32(const void* smem_ptr) {
    uint32_t addr;
    asm("{ .reg .u64 tmp; cvta.to.shared.u64 tmp, %1; cvt.u32.u64 %0, tmp; }"
        : "=r"(addr) : "l"(smem_ptr));
    return addr;
}

__device__ __forceinline__ void ldm_x4(uint32_t addr, uint32_t* r) {
    asm volatile("ldmatrix.sync.aligned.m8n8.x4.shared.b16 {%0,%1,%2,%3}, [%4];"
        : "=r"(r[0]), "=r"(r[1]), "=r"(r[2]), "=r"(r[3]) : "r"(addr));
}

__device__ __forceinline__ void mma_bf16(float* d, const uint32_t* a,
                                         uint32_t b0, uint32_t b1) {
    asm volatile(
        "mma.sync.aligned.m16n8k16.row.col.f32.bf16.bf16.f32 "
        "{%0,%1,%2,%3}, {%4,%5,%6,%7}, {%8,%9}, {%0,%1,%2,%3};"
        : "+f"(d[0]), "+f"(d[1]), "+f"(d[2]), "+f"(d[3])
        : "r"(a[0]), "r"(a[1]), "r"(a[2]), "r"(a[3]), "r"(b0), "r"(b1));
}

// ---------------------------------------------------------------------------
// Split fp32 -> bf16 hi/lo conversion kernels
// ---------------------------------------------------------------------------
__device__ __forceinline__ void split4_store(float4 v,
                                             __nv_bfloat16* __restrict__ hi,
                                             __nv_bfloat16* __restrict__ lo,
                                             size_t idx)
{
    float f[4] = {v.x, v.y, v.z, v.w};
    __nv_bfloat16 h[4], l[4];
#pragma unroll
    for (int t = 0; t < 4; ++t) {
        h[t] = __float2bfloat16(f[t]);
        l[t] = __float2bfloat16(f[t] - __bfloat162float(h[t]));
    }
    *(uint2*)(hi + idx) = *(uint2*)h;
    *(uint2*)(lo + idx) = *(uint2*)l;
}

__global__ __launch_bounds__(256)
void split_x_kernel(const float* __restrict__ src)
{
    int i = blockIdx.x * blockDim.x + threadIdx.x;
    float4 v = ((const float4*)src)[i];
    split4_store(v, g_xhi, g_xlo, (size_t)i * 4);
}

__global__ __launch_bounds__(256)
void split_w_kernel(const float* __restrict__ wq, const float* __restrict__ wk,
                    const float* __restrict__ wv, const float* __restrict__ wo)
{
    int which = blockIdx.y;
    const float* src = (which == 0) ? wq : (which == 1) ? wk : (which == 2) ? wv : wo;
    int i = blockIdx.x * blockDim.x + threadIdx.x;
    float4 v = ((const float4*)src)[i];
    split4_store(v, g_whi[which], g_wlo[which], (size_t)i * 4);
}

__global__ __launch_bounds__(256)
void split_att_kernel()
{
    int i = blockIdx.x * blockDim.x + threadIdx.x;
    float4 v = ((const float4*)g_att)[i];
    split4_store(v, g_ahi, g_alo, (size_t)i * 4);
}

// ---------------------------------------------------------------------------
// HMMA split-bf16 GEMM:  C[M,N] = A @ W^T + bias  (3-term hi/lo)
// Block tile 128x128, K-slab 32. 256 threads = 8 warps, warp tile 64x32.
// smem rows padded to 40 bf16 (80B stride -> conflict-free ldmatrix).
// ---------------------------------------------------------------------------
#define LDSB 40

__device__ __forceinline__ void hmma_gemm_body(
    const __nv_bfloat16* __restrict__ Ahi, const __nv_bfloat16* __restrict__ Alo,
    const __nv_bfloat16* __restrict__ Bhi, const __nv_bfloat16* __restrict__ Blo,
    const float* __restrict__ bias, float* __restrict__ C,
    int bm, int bn)
{
    __shared__ __nv_bfloat16 sAhi[128 * LDSB];
    __shared__ __nv_bfloat16 sAlo[128 * LDSB];
    __shared__ __nv_bfloat16 sBhi[128 * LDSB];
    __shared__ __nv_bfloat16 sBlo[128 * LDSB];

    const int tid  = threadIdx.x;
    const int wid  = tid >> 5;
    const int lane = tid & 31;

    const int warp_m = (wid & 1) * 64;    // 2 warps over M
    const int warp_n = (wid >> 1) * 32;   // 4 warps over N

    // ldmatrix lane address components
    const int a_row = lane & 15;              // m within 16
    const int a_ksel = (lane >> 4) * 8;       // k half
    const int b_row = (lane & 7) + ((lane >> 4) & 1) * 8;  // n within 16
    const int b_ksel = ((lane >> 3) & 1) * 8;              // k half

    const uint32_t sAhi_u = smem_u32(sAhi);
    const uint32_t sAlo_u = smem_u32(sAlo);
    const uint32_t sBhi_u = smem_u32(sBhi);
    const uint32_t sBlo_u = smem_u32(sBlo);

    const size_t arow0 = (size_t)bm * 128;
    const size_t brow0 = (size_t)bn * 128;

    float acc[4][4][4];
#pragma unroll
    for (int i = 0; i < 4; ++i)
#pragma unroll
        for (int j = 0; j < 4; ++j)
#pragma unroll
            for (int t = 0; t < 4; ++t) acc[i][j][t] = 0.f;

    for (int s = 0; s < DMODEL / 32; ++s) {
        const int kofs = s * 32;
        if (s > 0) __syncthreads();

        // load 128x32 slabs of Ahi/Alo/Bhi/Blo
#pragma unroll
        for (int it = 0; it < 2; ++it) {
            const int chunk = tid + it * 256;     // 0..511
            const int row = chunk >> 2;
            const int c8 = (chunk & 3) * 8;
            const size_t ga = (arow0 + row) * DMODEL + kofs + c8;
            const size_t gb = (brow0 + row) * DMODEL + kofs + c8;
            const int so = row * LDSB + c8;
            *(uint4*)(sAhi + so) = *(const uint4*)(Ahi + ga);
            *(uint4*)(sAlo + so) = *(const uint4*)(Alo + ga);
            *(uint4*)(sBhi + so) = *(const uint4*)(Bhi + gb);
            *(uint4*)(sBlo + so) = *(const uint4*)(Blo + gb);
        }
        __syncthreads();

#pragma unroll
        for (int kk = 0; kk < 2; ++kk) {
            const int kc = kk * 16;
            // B fragments: 4 n-tiles (two x4 loads per hi/lo)
            uint32_t bh[4][2], bl[4][2];
#pragma unroll
            for (int p = 0; p < 2; ++p) {
                uint32_t r[4];
                uint32_t boff = ((warp_n + p * 16 + b_row) * LDSB + kc + b_ksel) * 2;
                ldm_x4(sBhi_u + boff, r);
                bh[p * 2 + 0][0] = r[0]; bh[p * 2 + 0][1] = r[1];
                bh[p * 2 + 1][0] = r[2]; bh[p * 2 + 1][1] = r[3];
                ldm_x4(sBlo_u + boff, r);
                bl[p * 2 + 0][0] = r[0]; bl[p * 2 + 0][1] = r[1];
                bl[p * 2 + 1][0] = r[2]; bl[p * 2 + 1][1] = r[3];
            }
#pragma unroll
            for (int mt = 0; mt < 4; ++mt) {
                uint32_t aoff = ((warp_m + mt * 16 + a_row) * LDSB + kc + a_ksel) * 2;
                uint32_t ah[4], al[4];
                ldm_x4(sAhi_u + aoff, ah);
                ldm_x4(sAlo_u + aoff, al);
#pragma unroll
                for (int nt = 0; nt < 4; ++nt) {
                    mma_bf16(acc[mt][nt], ah, bh[nt][0], bh[nt][1]);  // hi*hi
                    mma_bf16(acc[mt][nt], ah, bl[nt][0], bl[nt][1]);  // hi*lo
                    mma_bf16(acc[mt][nt], al, bh[nt][0], bh[nt][1]);  // lo*hi
                }
            }
        }
    }

    // epilogue: d0,d1 -> row g, cols c,c+1 ; d2,d3 -> row g+8
    const int gq = lane >> 2;
    const int cq = (lane & 3) * 2;
#pragma unroll
    for (int mt = 0; mt < 4; ++mt) {
        const int r_lo = bm * 128 + warp_m + mt * 16 + gq;
#pragma unroll
        for (int nt = 0; nt < 4; ++nt) {
            const int c = bn * 128 + warp_n + nt * 8 + cq;
            const float b0 = bias[c], b1 = bias[c + 1];
            float2 v0 = make_float2(acc[mt][nt][0] + b0, acc[mt][nt][1] + b1);
            float2 v1 = make_float2(acc[mt][nt][2] + b0, acc[mt][nt][3] + b1);
            *(float2*)(C + (size_t)r_lo * DMODEL + c) = v0;
            *(float2*)(C + (size_t)(r_lo + 8) * DMODEL + c) = v1;
        }
    }
}

__global__ __launch_bounds__(256, 2)
void gemm_qkv_hmma(const float* __restrict__ bq, const float* __restrict__ bk,
                   const float* __restrict__ bv)
{
    const int z = blockIdx.z;
    const float* bias = (z == 0) ? bq : (z == 1) ? bk : bv;
    float* C = (z == 0) ? g_q : (z == 1) ? g_k : g_v;
    hmma_gemm_body(g_xhi, g_xlo, g_whi[z], g_wlo[z], bias, C,
                   blockIdx.y, blockIdx.x);
}

__global__ __launch_bounds__(256, 2)
void gemm_out_hmma(const float* __restrict__ bo, float* __restrict__ out)
{
    hmma_gemm_body(g_ahi, g_alo, g_whi[3], g_wlo[3], bo, out,
                   blockIdx.y, blockIdx.x);
}

// ---------------------------------------------------------------------------
// Flash attention (causal + key padding mask), fp32 — known-correct from R0.
// ---------------------------------------------------------------------------
__global__ __launch_bounds__(256)
void attn_kernel(const unsigned char* __restrict__ mask)
{
    __shared__ float Qt[64][64];
    __shared__ float KP[64][64];
    __shared__ float Vs[64][64];

    const int tid = threadIdx.x;
    const int qt  = blockIdx.x;
    const int bh  = blockIdx.y;
    const int b   = bh >> 4;
    const int h   = bh & 15;

    const int ty = tid >> 4, tx = tid & 15;
    const int r0 = ty << 2, c0 = tx << 2;

    const size_t headoff = (size_t)h * DHEAD;
    const float* Qg = g_q + ((size_t)(b * SEQ + qt * 64)) * DMODEL + headoff;
    const unsigned char* mb = mask + (size_t)b * SEQ;

    {
        const int lr = tid >> 4;
        const int ld = (tid & 15) << 2;
        #pragma unroll
        for (int it = 0; it < 4; ++it) {
            int r = lr + it * 16;
            float4 v = *(const float4*)(Qg + (size_t)r * DMODEL + ld);
            Qt[ld + 0][r] = v.x; Qt[ld + 1][r] = v.y;
            Qt[ld + 2][r] = v.z; Qt[ld + 3][r] = v.w;
        }
    }

    float mrow[4], lsum[4], acc[4][4];
    #pragma unroll
    for (int i = 0; i < 4; ++i) {
        mrow[i] = -1e30f; lsum[i] = 0.f;
        #pragma unroll
        for (int j = 0; j < 4; ++j) acc[i][j] = 0.f;
    }

    for (int j = 0; j <= qt; ++j) {
        __syncthreads();

        const float* Kg = g_k + ((size_t)(b * SEQ + j * 64)) * DMODEL + headoff;
        const float* Vg = g_v + ((size_t)(b * SEQ + j * 64)) * DMODEL + headoff;
        {
            const int lr = tid >> 4;
            const int ld = (tid & 15) << 2;
            #pragma unroll
            for (int it = 0; it < 4; ++it) {
                int r = lr + it * 16;
                float4 kv = *(const float4*)(Kg + (size_t)r * DMODEL + ld);
                KP[ld + 0][r] = kv.x; KP[ld + 1][r] = kv.y;
                KP[ld + 2][r] = kv.z; KP[ld + 3][r] = kv.w;
                float4 vv = *(const float4*)(Vg + (size_t)r * DMODEL + ld);
                *(float4*)&Vs[r][ld] = vv;
            }
        }
        __syncthreads();

        float s[4][4] = {};
        #pragma unroll 16
        for (int kk = 0; kk < 64; ++kk) {
            float4 av = *(const float4*)&Qt[kk][r0];
            float4 bv = *(const float4*)&KP[kk][c0];
            float a[4] = {av.x, av.y, av.z, av.w};
            float bb[4] = {bv.x, bv.y, bv.z, bv.w};
            #pragma unroll
            for (int i = 0; i < 4; ++i)
                #pragma unroll
                for (int jj = 0; jj < 4; ++jj)
                    s[i][jj] += a[i] * bb[jj];
        }

        const int qbase = qt * 64 + r0;
        const int kbase = j * 64 + c0;
        uchar4 m4 = *(const uchar4*)(mb + kbase);
        unsigned char mk[4] = {m4.x, m4.y, m4.z, m4.w};
        #pragma unroll
        for (int i = 0; i < 4; ++i)
            #pragma unroll
            for (int jj = 0; jj < 4; ++jj) {
                float v = s[i][jj] * 0.125f;
                if ((kbase + jj > qbase + i) || mk[jj]) v = -1e30f;
                s[i][jj] = v;
            }

        __syncthreads();

        #pragma unroll
        for (int i = 0; i < 4; ++i) {
            float tm = fmaxf(fmaxf(s[i][0], s[i][1]), fmaxf(s[i][2], s[i][3]));
            tm = fmaxf(tm, __shfl_xor_sync(0xffffffffu, tm, 8));
            tm = fmaxf(tm, __shfl_xor_sync(0xffffffffu, tm, 4));
            tm = fmaxf(tm, __shfl_xor_sync(0xffffffffu, tm, 2));
            tm = fmaxf(tm, __shfl_xor_sync(0xffffffffu, tm, 1));
            float mn = fmaxf(mrow[i], tm);
            mn = fmaxf(mn, -1e29f);
            float al = __expf(mrow[i] - mn);
            mrow[i] = mn;
            float ps = 0.f;
            #pragma unroll
            for (int jj = 0; jj < 4; ++jj) {
                float p = __expf(s[i][jj] - mn);
                s[i][jj] = p;
                ps += p;
            }
            ps += __shfl_xor_sync(0xffffffffu, ps, 8);
            ps += __shfl_xor_sync(0xffffffffu, ps, 4);
            ps += __shfl_xor_sync(0xffffffffu, ps, 2);
            ps += __shfl_xor_sync(0xffffffffu, ps, 1);
            lsum[i] = lsum[i] * al + ps;
            #pragma unroll
            for (int jj = 0; jj < 4; ++jj) acc[i][jj] *= al;
        }

        #pragma unroll
        for (int i = 0; i < 4; ++i)
            #pragma unroll
            for (int jj = 0; jj < 4; ++jj)
                KP[r0 + i][c0 + jj] = s[i][jj];

        __syncthreads();

        #pragma unroll 16
        for (int kk = 0; kk < 64; ++kk) {
            float4 bv = *(const float4*)&Vs[kk][c0];
            float bb[4] = {bv.x, bv.y, bv.z, bv.w};
            #pragma unroll
            for (int i = 0; i < 4; ++i) {
                float a = KP[r0 + i][kk];
                #pragma unroll
                for (int jj = 0; jj < 4; ++jj)
                    acc[i][jj] += a * bb[jj];
            }
        }
    }

    float* Og = g_att + ((size_t)(b * SEQ + qt * 64)) * DMODEL + headoff;
    #pragma unroll
    for (int i = 0; i < 4; ++i) {
        float inv = 1.0f / lsum[i];
        float4 o;
        o.x = acc[i][0] * inv; o.y = acc[i][1] * inv;
        o.z = acc[i][2] * inv; o.w = acc[i][3] * inv;
        *(float4*)(Og + (size_t)(r0 + i) * DMODEL + c0) = o;
    }
}

// ---------------------------------------------------------------------------
extern "C" void kernel_launch(void* const* d_in, const int* in_sizes, int n_in,
                              void* d_out, int out_size)
{
    const float*         x    = (const float*)d_in[0];
    const unsigned char* mask = (const unsigned char*)d_in[1];
    const float*         wq   = (const float*)d_in[2];
    const float*         bq   = (const float*)d_in[3];
    const float*         wk   = (const float*)d_in[4];
    const float*         bk   = (const float*)d_in[5];
    const float*         wv   = (const float*)d_in[6];
    const float*         bv   = (const float*)d_in[7];
    const float*         wo   = (const float*)d_in[8];
    const float*         bo   = (const float*)d_in[9];
    float*               out  = (float*)d_out;

    // split inputs to bf16 hi/lo
    split_x_kernel<<<MROWS * DMODEL / 4 / 256, 256>>>(x);
    split_w_kernel<<<dim3(DMODEL * DMODEL / 4 / 256, 4), 256>>>(wq, wk, wv, wo);

    // QKV projections on HMMA
    gemm_qkv_hmma<<<dim3(DMODEL / 128, MROWS / 128, 3), 256>>>(bq, bk, bv);

    // attention (fp32)
    attn_kernel<<<dim3(SEQ / 64, BATCH * NHEADS), 256>>>(mask);

    // split attention output, then output projection on HMMA
    split_att_kernel<<<MROWS * DMODEL / 4 / 256, 256>>>();
    gemm_out_hmma<<<dim3(DMODEL / 128, MROWS / 128), 256>>>(bo, out);
}

// round 4
// speedup vs baseline: 3.8978x; 1.5680x over previous
#include <cuda_runtime.h>
#include <cuda_bf16.h>
#include <stdint.h>
#include <math.h>

// Problem constants
#define BATCH   2
#define SEQ     2048
#define DMODEL  1024
#define NHEADS  16
#define DHEAD   64
#define MROWS   (BATCH * SEQ)     // 4096 tokens

// ---------------------------------------------------------------------------
// Device-global scratch (allocation-free)
// ---------------------------------------------------------------------------
__device__ __nv_bfloat16 g_xhi[MROWS * DMODEL];
__device__ __nv_bfloat16 g_xlo[MROWS * DMODEL];
__device__ __nv_bfloat16 g_qhi[MROWS * DMODEL];
__device__ __nv_bfloat16 g_qlo[MROWS * DMODEL];
__device__ __nv_bfloat16 g_khi[MROWS * DMODEL];
__device__ __nv_bfloat16 g_klo[MROWS * DMODEL];
__device__ __nv_bfloat16 g_vhi[MROWS * DMODEL];
__device__ __nv_bfloat16 g_vlo[MROWS * DMODEL];
__device__ __nv_bfloat16 g_ahi[MROWS * DMODEL];
__device__ __nv_bfloat16 g_alo[MROWS * DMODEL];
__device__ __nv_bfloat16 g_whi[4][DMODEL * DMODEL];
__device__ __nv_bfloat16 g_wlo[4][DMODEL * DMODEL];

// ---------------------------------------------------------------------------
// warp-mma helpers (plain sm_80-class PTX; compiles at compute_103)
// ---------------------------------------------------------------------------
__device__ __forceinline__ uint32_t smem_u32(const void* smem_ptr) {
    uint32_t addr;
    asm("{ .reg .u64 tmp; cvta.to.shared.u64 tmp, %1; cvt.u32.u64 %0, tmp; }"
        : "=r"(addr) : "l"(smem_ptr));
    return addr;
}

__device__ __forceinline__ void ldm_x4(uint32_t addr, uint32_t* r) {
    asm volatile("ldmatrix.sync.aligned.m8n8.x4.shared.b16 {%0,%1,%2,%3}, [%4];"
        : "=r"(r[0]), "=r"(r[1]), "=r"(r[2]), "=r"(r[3]) : "r"(addr));
}

__device__ __forceinline__ void mma_bf16(float* d, const uint32_t* a,
                                         uint32_t b0, uint32_t b1) {
    asm volatile(
        "mma.sync.aligned.m16n8k16.row.col.f32.bf16.bf16.f32 "
        "{%0,%1,%2,%3}, {%4,%5,%6,%7}, {%8,%9}, {%0,%1,%2,%3};"
        : "+f"(d[0]), "+f"(d[1]), "+f"(d[2]), "+f"(d[3])
        : "r"(a[0]), "r"(a[1]), "r"(a[2]), "r"(a[3]), "r"(b0), "r"(b1));
}

// pack two floats into bf16x2 hi plus bf16x2 residual lo
__device__ __forceinline__ void split_pack(float f0, float f1,
                                           uint32_t& hi, uint32_t& lo) {
    __nv_bfloat162 h = __floats2bfloat162_rn(f0, f1);
    hi = *reinterpret_cast<uint32_t*>(&h);
    __nv_bfloat162 l = __floats2bfloat162_rn(f0 - __bfloat162float(h.x),
                                             f1 - __bfloat162float(h.y));
    lo = *reinterpret_cast<uint32_t*>(&l);
}

// ---------------------------------------------------------------------------
// Split fp32 -> bf16 hi/lo conversion kernels
// ---------------------------------------------------------------------------
__device__ __forceinline__ void split4_store(float4 v,
                                             __nv_bfloat16* __restrict__ hi,
                                             __nv_bfloat16* __restrict__ lo,
                                             size_t idx)
{
    float f[4] = {v.x, v.y, v.z, v.w};
    __nv_bfloat16 h[4], l[4];
#pragma unroll
    for (int t = 0; t < 4; ++t) {
        h[t] = __float2bfloat16(f[t]);
        l[t] = __float2bfloat16(f[t] - __bfloat162float(h[t]));
    }
    *(uint2*)(hi + idx) = *(uint2*)h;
    *(uint2*)(lo + idx) = *(uint2*)l;
}

__global__ __launch_bounds__(256)
void split_x_kernel(const float* __restrict__ src)
{
    int i = blockIdx.x * blockDim.x + threadIdx.x;
    float4 v = ((const float4*)src)[i];
    split4_store(v, g_xhi, g_xlo, (size_t)i * 4);
}

__global__ __launch_bounds__(256)
void split_w_kernel(const float* __restrict__ wq, const float* __restrict__ wk,
                    const float* __restrict__ wv, const float* __restrict__ wo)
{
    int which = blockIdx.y;
    const float* src = (which == 0) ? wq : (which == 1) ? wk : (which == 2) ? wv : wo;
    int i = blockIdx.x * blockDim.x + threadIdx.x;
    float4 v = ((const float4*)src)[i];
    split4_store(v, g_whi[which], g_wlo[which], (size_t)i * 4);
}

// ---------------------------------------------------------------------------
// HMMA split-bf16 GEMM:  C[M,N] = A @ W^T + bias  (3-term hi/lo)
// Block tile 128x128, K-slab 32. 256 threads = 8 warps, warp tile 64x32.
// SPLIT=true  -> write bf16 hi/lo outputs (for q/k/v feeding attention)
// SPLIT=false -> write fp32 output (final projection)
// ---------------------------------------------------------------------------
#define LDSB 40

template<bool SPLIT>
__device__ __forceinline__ void hmma_gemm_body(
    const __nv_bfloat16* __restrict__ Ahi, const __nv_bfloat16* __restrict__ Alo,
    const __nv_bfloat16* __restrict__ Bhi, const __nv_bfloat16* __restrict__ Blo,
    const float* __restrict__ bias, float* __restrict__ C,
    __nv_bfloat16* __restrict__ Chi, __nv_bfloat16* __restrict__ Clo,
    int bm, int bn)
{
    __shared__ __nv_bfloat16 sAhi[128 * LDSB];
    __shared__ __nv_bfloat16 sAlo[128 * LDSB];
    __shared__ __nv_bfloat16 sBhi[128 * LDSB];
    __shared__ __nv_bfloat16 sBlo[128 * LDSB];

    const int tid  = threadIdx.x;
    const int wid  = tid >> 5;
    const int lane = tid & 31;

    const int warp_m = (wid & 1) * 64;
    const int warp_n = (wid >> 1) * 32;

    const int a_row = lane & 15;
    const int a_ksel = (lane >> 4) * 8;
    const int b_row = (lane & 7) + ((lane >> 4) & 1) * 8;
    const int b_ksel = ((lane >> 3) & 1) * 8;

    const uint32_t sAhi_u = smem_u32(sAhi);
    const uint32_t sAlo_u = smem_u32(sAlo);
    const uint32_t sBhi_u = smem_u32(sBhi);
    const uint32_t sBlo_u = smem_u32(sBlo);

    const size_t arow0 = (size_t)bm * 128;
    const size_t brow0 = (size_t)bn * 128;

    float acc[4][4][4];
#pragma unroll
    for (int i = 0; i < 4; ++i)
#pragma unroll
        for (int j = 0; j < 4; ++j)
#pragma unroll
            for (int t = 0; t < 4; ++t) acc[i][j][t] = 0.f;

    for (int s = 0; s < DMODEL / 32; ++s) {
        const int kofs = s * 32;
        if (s > 0) __syncthreads();

#pragma unroll
        for (int it = 0; it < 2; ++it) {
            const int chunk = tid + it * 256;
            const int row = chunk >> 2;
            const int c8 = (chunk & 3) * 8;
            const size_t ga = (arow0 + row) * DMODEL + kofs + c8;
            const size_t gb = (brow0 + row) * DMODEL + kofs + c8;
            const int so = row * LDSB + c8;
            *(uint4*)(sAhi + so) = *(const uint4*)(Ahi + ga);
            *(uint4*)(sAlo + so) = *(const uint4*)(Alo + ga);
            *(uint4*)(sBhi + so) = *(const uint4*)(Bhi + gb);
            *(uint4*)(sBlo + so) = *(const uint4*)(Blo + gb);
        }
        __syncthreads();

#pragma unroll
        for (int kk = 0; kk < 2; ++kk) {
            const int kc = kk * 16;
            uint32_t bh[4][2], bl[4][2];
#pragma unroll
            for (int p = 0; p < 2; ++p) {
                uint32_t r[4];
                uint32_t boff = ((warp_n + p * 16 + b_row) * LDSB + kc + b_ksel) * 2;
                ldm_x4(sBhi_u + boff, r);
                bh[p * 2 + 0][0] = r[0]; bh[p * 2 + 0][1] = r[1];
                bh[p * 2 + 1][0] = r[2]; bh[p * 2 + 1][1] = r[3];
                ldm_x4(sBlo_u + boff, r);
                bl[p * 2 + 0][0] = r[0]; bl[p * 2 + 0][1] = r[1];
                bl[p * 2 + 1][0] = r[2]; bl[p * 2 + 1][1] = r[3];
            }
#pragma unroll
            for (int mt = 0; mt < 4; ++mt) {
                uint32_t aoff = ((warp_m + mt * 16 + a_row) * LDSB + kc + a_ksel) * 2;
                uint32_t ah[4], al[4];
                ldm_x4(sAhi_u + aoff, ah);
                ldm_x4(sAlo_u + aoff, al);
#pragma unroll
                for (int nt = 0; nt < 4; ++nt) {
                    mma_bf16(acc[mt][nt], ah, bh[nt][0], bh[nt][1]);
                    mma_bf16(acc[mt][nt], ah, bl[nt][0], bl[nt][1]);
                    mma_bf16(acc[mt][nt], al, bh[nt][0], bh[nt][1]);
                }
            }
        }
    }

    const int gq = lane >> 2;
    const int cq = (lane & 3) * 2;
#pragma unroll
    for (int mt = 0; mt < 4; ++mt) {
        const int r_lo = bm * 128 + warp_m + mt * 16 + gq;
#pragma unroll
        for (int nt = 0; nt < 4; ++nt) {
            const int c = bn * 128 + warp_n + nt * 8 + cq;
            const float b0 = bias[c], b1 = bias[c + 1];
            float v0 = acc[mt][nt][0] + b0, v1 = acc[mt][nt][1] + b1;
            float v2 = acc[mt][nt][2] + b0, v3 = acc[mt][nt][3] + b1;
            if (SPLIT) {
                uint32_t h0, l0, h1, l1;
                split_pack(v0, v1, h0, l0);
                split_pack(v2, v3, h1, l1);
                *(uint32_t*)(Chi + (size_t)r_lo * DMODEL + c) = h0;
                *(uint32_t*)(Clo + (size_t)r_lo * DMODEL + c) = l0;
                *(uint32_t*)(Chi + (size_t)(r_lo + 8) * DMODEL + c) = h1;
                *(uint32_t*)(Clo + (size_t)(r_lo + 8) * DMODEL + c) = l1;
            } else {
                *(float2*)(C + (size_t)r_lo * DMODEL + c) = make_float2(v0, v1);
                *(float2*)(C + (size_t)(r_lo + 8) * DMODEL + c) = make_float2(v2, v3);
            }
        }
    }
}

__global__ __launch_bounds__(256, 2)
void gemm_qkv_hmma(const float* __restrict__ bq, const float* __restrict__ bk,
                   const float* __restrict__ bv)
{
    const int z = blockIdx.z;
    const float* bias = (z == 0) ? bq : (z == 1) ? bk : bv;
    __nv_bfloat16* Chi = (z == 0) ? g_qhi : (z == 1) ? g_khi : g_vhi;
    __nv_bfloat16* Clo = (z == 0) ? g_qlo : (z == 1) ? g_klo : g_vlo;
    hmma_gemm_body<true>(g_xhi, g_xlo, g_whi[z], g_wlo[z], bias,
                         nullptr, Chi, Clo, blockIdx.y, blockIdx.x);
}

__global__ __launch_bounds__(256, 2)
void gemm_out_hmma(const float* __restrict__ bo, float* __restrict__ out)
{
    hmma_gemm_body<false>(g_ahi, g_alo, g_whi[3], g_wlo[3], bo,
                          out, nullptr, nullptr, blockIdx.y, blockIdx.x);
}

// ---------------------------------------------------------------------------
// HMMA flash attention (causal + key padding), split-bf16 3-term.
// Block: 128 threads = 4 warps, 64 q-rows (16 per warp). KV tiles of 64.
// smem: Q hi/lo [64][72], K hi/lo [64][72], V^T hi/lo [64 dh][72 kv], bias[64].
// ---------------------------------------------------------------------------
#define ALDS 72
#define A_QH   0
#define A_QL   9216
#define A_KH   18432
#define A_KL   27648
#define A_VH   36864
#define A_VL   46080
#define A_BIAS 55296
#define A_TOTAL 55808

__global__ __launch_bounds__(128)
void attn_hmma(const unsigned char* __restrict__ mask)
{
    extern __shared__ char smem[];
    float* sbias = (float*)(smem + A_BIAS);

    const int tid  = threadIdx.x;
    const int wid  = tid >> 5;
    const int lane = tid & 31;

    const int qt = (int)gridDim.x - 1 - (int)blockIdx.x;  // reversed: big first
    const int bh = blockIdx.y;
    const int b  = bh >> 4;
    const int h  = bh & 15;
    const int q0 = qt * 64;

    const size_t qbase = (size_t)(b * SEQ + q0) * DMODEL + h * DHEAD;
    const unsigned char* mb = mask + (size_t)b * SEQ;

    // ---- load Q tile (hi/lo) to smem ----
#pragma unroll
    for (int it = 0; it < 4; ++it) {
        const int idx = tid + it * 128;      // 0..511
        const int row = idx >> 3;
        const int c8  = (idx & 7) * 8;
        *(uint4*)(smem + A_QH + (row * ALDS + c8) * 2) =
            *(const uint4*)(g_qhi + qbase + (size_t)row * DMODEL + c8);
        *(uint4*)(smem + A_QL + (row * ALDS + c8) * 2) =
            *(const uint4*)(g_qlo + qbase + (size_t)row * DMODEL + c8);
    }
    __syncthreads();

    // ---- preload Q fragments ----
    const int a_row  = lane & 15;
    const int a_ksel = (lane >> 4) * 8;
    const int b_row  = (lane & 7) + ((lane >> 4) & 1) * 8;
    const int b_ksel = ((lane >> 3) & 1) * 8;
    const uint32_t smb = smem_u32(smem);

    uint32_t qh[4][4], ql[4][4];
#pragma unroll
    for (int kk = 0; kk < 4; ++kk) {
        const uint32_t off = ((wid * 16 + a_row) * ALDS + kk * 16 + a_ksel) * 2;
        ldm_x4(smb + A_QH + off, qh[kk]);
        ldm_x4(smb + A_QL + off, ql[kk]);
    }

    // ---- softmax state + O accumulator ----
    float mA = -1e30f, mB = -1e30f, lA = 0.f, lB = 0.f;
    float o[8][4];
#pragma unroll
    for (int nt = 0; nt < 8; ++nt)
#pragma unroll
        for (int t = 0; t < 4; ++t) o[nt][t] = 0.f;

    const int rowA = q0 + wid * 16 + (lane >> 2);
    const int rowB = rowA + 8;
    const float SC = 0.125f * 1.44269504f;   // (1/sqrt(64)) * log2(e)

    for (int j = 0; j <= qt; ++j) {
        __syncthreads();   // previous tile's smem reads complete

        // ---- load K (row-major) and V (transposed) tiles, hi/lo ----
        const size_t kvb = (size_t)(b * SEQ + j * 64) * DMODEL + h * DHEAD;
#pragma unroll
        for (int it = 0; it < 4; ++it) {
            const int idx = tid + it * 128;
            const int row = idx >> 3;
            const int c8  = (idx & 7) * 8;
            const size_t g = kvb + (size_t)row * DMODEL + c8;
            *(uint4*)(smem + A_KH + (row * ALDS + c8) * 2) = *(const uint4*)(g_khi + g);
            *(uint4*)(smem + A_KL + (row * ALDS + c8) * 2) = *(const uint4*)(g_klo + g);
            uint4 vh = *(const uint4*)(g_vhi + g);
            uint4 vl = *(const uint4*)(g_vlo + g);
            const __nv_bfloat16* vhp = (const __nv_bfloat16*)&vh;
            const __nv_bfloat16* vlp = (const __nv_bfloat16*)&vl;
#pragma unroll
            for (int t = 0; t < 8; ++t) {
                *(__nv_bfloat16*)(smem + A_VH + ((c8 + t) * ALDS + row) * 2) = vhp[t];
                *(__nv_bfloat16*)(smem + A_VL + ((c8 + t) * ALDS + row) * 2) = vlp[t];
            }
        }
        if (tid < 64)
            sbias[tid] = mb[j * 64 + tid] ? -1e30f : 0.f;
        __syncthreads();

        // ---- S = Q K^T (3-term) ----
        float s[8][4];
#pragma unroll
        for (int nt = 0; nt < 8; ++nt)
#pragma unroll
            for (int t = 0; t < 4; ++t) s[nt][t] = 0.f;

#pragma unroll
        for (int kk = 0; kk < 4; ++kk) {
            const int kc = kk * 16;
#pragma unroll
            for (int p = 0; p < 4; ++p) {
                uint32_t bh4[4], bl4[4];
                const uint32_t boff = ((p * 16 + b_row) * ALDS + kc + b_ksel) * 2;
                ldm_x4(smb + A_KH + boff, bh4);
                ldm_x4(smb + A_KL + boff, bl4);
                mma_bf16(s[2 * p],     qh[kk], bh4[0], bh4[1]);
                mma_bf16(s[2 * p + 1], qh[kk], bh4[2], bh4[3]);
                mma_bf16(s[2 * p],     qh[kk], bl4[0], bl4[1]);
                mma_bf16(s[2 * p + 1], qh[kk], bl4[2], bl4[3]);
                mma_bf16(s[2 * p],     ql[kk], bh4[0], bh4[1]);
                mma_bf16(s[2 * p + 1], ql[kk], bh4[2], bh4[3]);
            }
        }

        // ---- scale + padding bias + causal (diag tile only) ----
        const bool diag = (j == qt);
#pragma unroll
        for (int nt = 0; nt < 8; ++nt) {
            const float2 bia = *(const float2*)&sbias[nt * 8 + (lane & 3) * 2];
            s[nt][0] = s[nt][0] * SC + bia.x;
            s[nt][1] = s[nt][1] * SC + bia.y;
            s[nt][2] = s[nt][2] * SC + bia.x;
            s[nt][3] = s[nt][3] * SC + bia.y;
            if (diag) {
                const int c0g = j * 64 + nt * 8 + (lane & 3) * 2;
                if (c0g     > rowA) s[nt][0] = -1e30f;
                if (c0g + 1 > rowA) s[nt][1] = -1e30f;
                if (c0g     > rowB) s[nt][2] = -1e30f;
                if (c0g + 1 > rowB) s[nt][3] = -1e30f;
            }
        }

        // ---- online softmax (rows A = lane>>2, B = +8; quad reduction) ----
        float tmA = -1e30f, tmB = -1e30f;
#pragma unroll
        for (int nt = 0; nt < 8; ++nt) {
            tmA = fmaxf(tmA, fmaxf(s[nt][0], s[nt][1]));
            tmB = fmaxf(tmB, fmaxf(s[nt][2], s[nt][3]));
        }
        tmA = fmaxf(tmA, __shfl_xor_sync(0xffffffffu, tmA, 1));
        tmA = fmaxf(tmA, __shfl_xor_sync(0xffffffffu, tmA, 2));
        tmB = fmaxf(tmB, __shfl_xor_sync(0xffffffffu, tmB, 1));
        tmB = fmaxf(tmB, __shfl_xor_sync(0xffffffffu, tmB, 2));

        const float mnA = fmaxf(mA, tmA);
        const float mnB = fmaxf(mB, tmB);
        const float alA = exp2f(mA - mnA);
        const float alB = exp2f(mB - mnB);
        mA = mnA; mB = mnB;

        float psA = 0.f, psB = 0.f;
#pragma unroll
        for (int nt = 0; nt < 8; ++nt) {
            s[nt][0] = exp2f(s[nt][0] - mA);
            s[nt][1] = exp2f(s[nt][1] - mA);
            s[nt][2] = exp2f(s[nt][2] - mB);
            s[nt][3] = exp2f(s[nt][3] - mB);
            psA += s[nt][0] + s[nt][1];
            psB += s[nt][2] + s[nt][3];
        }
        psA += __shfl_xor_sync(0xffffffffu, psA, 1);
        psA += __shfl_xor_sync(0xffffffffu, psA, 2);
        psB += __shfl_xor_sync(0xffffffffu, psB, 1);
        psB += __shfl_xor_sync(0xffffffffu, psB, 2);
        lA = lA * alA + psA;
        lB = lB * alB + psB;

#pragma unroll
        for (int nt = 0; nt < 8; ++nt) {
            o[nt][0] *= alA; o[nt][1] *= alA;
            o[nt][2] *= alB; o[nt][3] *= alB;
        }

        // ---- O += P V  (P split hi/lo from registers; V^T from smem) ----
#pragma unroll
        for (int t = 0; t < 4; ++t) {
            uint32_t ah4[4], al4[4];
            split_pack(s[2 * t][0],     s[2 * t][1],     ah4[0], al4[0]);
            split_pack(s[2 * t][2],     s[2 * t][3],     ah4[1], al4[1]);
            split_pack(s[2 * t + 1][0], s[2 * t + 1][1], ah4[2], al4[2]);
            split_pack(s[2 * t + 1][2], s[2 * t + 1][3], ah4[3], al4[3]);
#pragma unroll
            for (int p = 0; p < 4; ++p) {
                uint32_t vh4[4], vl4[4];
                const uint32_t voff = ((p * 16 + b_row) * ALDS + t * 16 + b_ksel) * 2;
                ldm_x4(smb + A_VH + voff, vh4);
                ldm_x4(smb + A_VL + voff, vl4);
                mma_bf16(o[2 * p],     ah4, vh4[0], vh4[1]);
                mma_bf16(o[2 * p + 1], ah4, vh4[2], vh4[3]);
                mma_bf16(o[2 * p],     ah4, vl4[0], vl4[1]);
                mma_bf16(o[2 * p + 1], ah4, vl4[2], vl4[3]);
                mma_bf16(o[2 * p],     al4, vh4[0], vh4[1]);
                mma_bf16(o[2 * p + 1], al4, vh4[2], vh4[3]);
            }
        }
    }

    // ---- epilogue: normalize, split to bf16 hi/lo for out-projection ----
    const float invA = 1.0f / lA;
    const float invB = 1.0f / lB;
    const size_t grA = (size_t)(b * SEQ + rowA) * DMODEL;
    const size_t grB = (size_t)(b * SEQ + rowB) * DMODEL;
#pragma unroll
    for (int nt = 0; nt < 8; ++nt) {
        const int col = h * DHEAD + nt * 8 + (lane & 3) * 2;
        uint32_t h0, l0, h1, l1;
        split_pack(o[nt][0] * invA, o[nt][1] * invA, h0, l0);
        split_pack(o[nt][2] * invB, o[nt][3] * invB, h1, l1);
        *(uint32_t*)(g_ahi + grA + col) = h0;
        *(uint32_t*)(g_alo + grA + col) = l0;
        *(uint32_t*)(g_ahi + grB + col) = h1;
        *(uint32_t*)(g_alo + grB + col) = l1;
    }
}

// ---------------------------------------------------------------------------
extern "C" void kernel_launch(void* const* d_in, const int* in_sizes, int n_in,
                              void* d_out, int out_size)
{
    const float*         x    = (const float*)d_in[0];
    const unsigned char* mask = (const unsigned char*)d_in[1];
    const float*         wq   = (const float*)d_in[2];
    const float*         bq   = (const float*)d_in[3];
    const float*         wk   = (const float*)d_in[4];
    const float*         bk   = (const float*)d_in[5];
    const float*         wv   = (const float*)d_in[6];
    const float*         bv   = (const float*)d_in[7];
    const float*         wo   = (const float*)d_in[8];
    const float*         bo   = (const float*)d_in[9];
    float*               out  = (float*)d_out;

    cudaFuncSetAttribute(attn_hmma,
                         cudaFuncAttributeMaxDynamicSharedMemorySize, A_TOTAL);

    // split inputs to bf16 hi/lo
    split_x_kernel<<<MROWS * DMODEL / 4 / 256, 256>>>(x);
    split_w_kernel<<<dim3(DMODEL * DMODEL / 4 / 256, 4), 256>>>(wq, wk, wv, wo);

    // QKV projections on HMMA (write split bf16 directly)
    gemm_qkv_hmma<<<dim3(DMODEL / 128, MROWS / 128, 3), 256>>>(bq, bk, bv);

    // flash attention on HMMA (writes split bf16 directly)
    attn_hmma<<<dim3(SEQ / 64, BATCH * NHEADS), 128, A_TOTAL>>>(mask);

    // output projection on HMMA
    gemm_out_hmma<<<dim3(DMODEL / 128, MROWS / 128), 256>>>(bo, out);
}

// round 5
// speedup vs baseline: 4.9837x; 1.2786x over previous
#include <cuda_runtime.h>
#include <cuda_bf16.h>
#include <stdint.h>
#include <math.h>

// Problem constants
#define BATCH   2
#define SEQ     2048
#define DMODEL  1024
#define NHEADS  16
#define DHEAD   64
#define MROWS   (BATCH * SEQ)     // 4096 tokens

// ---------------------------------------------------------------------------
// Device-global scratch (allocation-free)
// ---------------------------------------------------------------------------
__device__ __nv_bfloat16 g_xhi[MROWS * DMODEL];
__device__ __nv_bfloat16 g_xlo[MROWS * DMODEL];
__device__ __nv_bfloat16 g_qhi[MROWS * DMODEL];
__device__ __nv_bfloat16 g_qlo[MROWS * DMODEL];
__device__ __nv_bfloat16 g_khi[MROWS * DMODEL];
__device__ __nv_bfloat16 g_klo[MROWS * DMODEL];
__device__ __nv_bfloat16 g_vhi[MROWS * DMODEL];
__device__ __nv_bfloat16 g_vlo[MROWS * DMODEL];
__device__ __nv_bfloat16 g_ahi[MROWS * DMODEL];
__device__ __nv_bfloat16 g_alo[MROWS * DMODEL];
__device__ __nv_bfloat16 g_whi[4][DMODEL * DMODEL];
__device__ __nv_bfloat16 g_wlo[4][DMODEL * DMODEL];

// ---------------------------------------------------------------------------
// warp-mma / async-copy helpers (sm_80-class PTX; compiles at compute_103)
// ---------------------------------------------------------------------------
__device__ __forceinline__ uint32_t smem_u32(const void* smem_ptr) {
    uint32_t addr;
    asm("{ .reg .u64 tmp; cvta.to.shared.u64 tmp, %1; cvt.u32.u64 %0, tmp; }"
        : "=r"(addr) : "l"(smem_ptr));
    return addr;
}

__device__ __forceinline__ void ldm_x4(uint32_t addr, uint32_t* r) {
    asm volatile("ldmatrix.sync.aligned.m8n8.x4.shared.b16 {%0,%1,%2,%3}, [%4];"
        : "=r"(r[0]), "=r"(r[1]), "=r"(r[2]), "=r"(r[3]) : "r"(addr));
}

__device__ __forceinline__ void ldm_x4_trans(uint32_t addr, uint32_t* r) {
    asm volatile("ldmatrix.sync.aligned.m8n8.x4.trans.shared.b16 {%0,%1,%2,%3}, [%4];"
        : "=r"(r[0]), "=r"(r[1]), "=r"(r[2]), "=r"(r[3]) : "r"(addr));
}

__device__ __forceinline__ void mma_bf16(float* d, const uint32_t* a,
                                         uint32_t b0, uint32_t b1) {
    asm volatile(
        "mma.sync.aligned.m16n8k16.row.col.f32.bf16.bf16.f32 "
        "{%0,%1,%2,%3}, {%4,%5,%6,%7}, {%8,%9}, {%0,%1,%2,%3};"
        : "+f"(d[0]), "+f"(d[1]), "+f"(d[2]), "+f"(d[3])
        : "r"(a[0]), "r"(a[1]), "r"(a[2]), "r"(a[3]), "r"(b0), "r"(b1));
}

__device__ __forceinline__ void cp16(uint32_t saddr, const void* g) {
    asm volatile("cp.async.cg.shared.global [%0], [%1], 16;"
                 :: "r"(saddr), "l"(g));
}
#define CP_COMMIT() asm volatile("cp.async.commit_group;" ::: "memory")
#define CP_WAIT_ALL() asm volatile("cp.async.wait_group 0;" ::: "memory")

// pack two floats into bf16x2 hi plus bf16x2 residual lo
__device__ __forceinline__ void split_pack(float f0, float f1,
                                           uint32_t& hi, uint32_t& lo) {
    __nv_bfloat162 h = __floats2bfloat162_rn(f0, f1);
    hi = *reinterpret_cast<uint32_t*>(&h);
    __nv_bfloat162 l = __floats2bfloat162_rn(f0 - __bfloat162float(h.x),
                                             f1 - __bfloat162float(h.y));
    lo = *reinterpret_cast<uint32_t*>(&l);
}

// ---------------------------------------------------------------------------
// Split fp32 -> bf16 hi/lo conversion kernels
// ---------------------------------------------------------------------------
__device__ __forceinline__ void split4_store(float4 v,
                                             __nv_bfloat16* __restrict__ hi,
                                             __nv_bfloat16* __restrict__ lo,
                                             size_t idx)
{
    float f[4] = {v.x, v.y, v.z, v.w};
    __nv_bfloat16 h[4], l[4];
#pragma unroll
    for (int t = 0; t < 4; ++t) {
        h[t] = __float2bfloat16(f[t]);
        l[t] = __float2bfloat16(f[t] - __bfloat162float(h[t]));
    }
    *(uint2*)(hi + idx) = *(uint2*)h;
    *(uint2*)(lo + idx) = *(uint2*)l;
}

__global__ __launch_bounds__(256)
void split_x_kernel(const float* __restrict__ src)
{
    int i = blockIdx.x * blockDim.x + threadIdx.x;
    float4 v = ((const float4*)src)[i];
    split4_store(v, g_xhi, g_xlo, (size_t)i * 4);
}

__global__ __launch_bounds__(256)
void split_w_kernel(const float* __restrict__ wq, const float* __restrict__ wk,
                    const float* __restrict__ wv, const float* __restrict__ wo)
{
    int which = blockIdx.y;
    const float* src = (which == 0) ? wq : (which == 1) ? wk : (which == 2) ? wv : wo;
    int i = blockIdx.x * blockDim.x + threadIdx.x;
    float4 v = ((const float4*)src)[i];
    split4_store(v, g_whi[which], g_wlo[which], (size_t)i * 4);
}

// ---------------------------------------------------------------------------
// HMMA split-bf16 GEMM with cp.async double buffering.
// Block tile 128x128, K-slab 32. 256 threads = 8 warps, warp tile 64x32.
// Dynamic smem: 2 stages x (Ahi|Alo|Bhi|Blo), each 128*40 bf16 = 10240 B.
// ---------------------------------------------------------------------------
#define LDSB 40
#define G_ARR   10240
#define G_STAGE 40960
#define G_TOTAL 81920

template<bool SPLIT>
__device__ __forceinline__ void hmma_gemm_body(
    const __nv_bfloat16* __restrict__ Ahi, const __nv_bfloat16* __restrict__ Alo,
    const __nv_bfloat16* __restrict__ Bhi, const __nv_bfloat16* __restrict__ Blo,
    const float* __restrict__ bias, float* __restrict__ C,
    __nv_bfloat16* __restrict__ Chi, __nv_bfloat16* __restrict__ Clo,
    int bm, int bn)
{
    extern __shared__ char gsm[];
    const uint32_t smb = smem_u32(gsm);

    const int tid  = threadIdx.x;
    const int wid  = tid >> 5;
    const int lane = tid & 31;

    const int warp_m = (wid & 1) * 64;
    const int warp_n = (wid >> 1) * 32;

    const int a_row = lane & 15;
    const int a_ksel = (lane >> 4) * 8;
    const int b_row = (lane & 7) + ((lane >> 4) & 1) * 8;
    const int b_ksel = ((lane >> 3) & 1) * 8;

    const size_t arow0 = (size_t)bm * 128;
    const size_t brow0 = (size_t)bn * 128;

    // per-thread load coords (2 chunks)
    const int row0 = tid >> 2;           // chunk = tid
    const int c80  = (tid & 3) * 8;
    const int row1 = (tid + 256) >> 2;
    const int c81  = c80;

    float acc[4][4][4];
#pragma unroll
    for (int i = 0; i < 4; ++i)
#pragma unroll
        for (int j = 0; j < 4; ++j)
#pragma unroll
            for (int t = 0; t < 4; ++t) acc[i][j][t] = 0.f;

    // prefetch slab 0 into stage 0
    {
        const int kofs = 0;
        const uint32_t st = smb;
#pragma unroll
        for (int it = 0; it < 2; ++it) {
            const int row = it ? row1 : row0;
            const int c8  = it ? c81 : c80;
            const size_t ga = (arow0 + row) * DMODEL + kofs + c8;
            const size_t gb = (brow0 + row) * DMODEL + kofs + c8;
            const uint32_t so = (row * LDSB + c8) * 2;
            cp16(st + so,             Ahi + ga);
            cp16(st + G_ARR + so,     Alo + ga);
            cp16(st + 2 * G_ARR + so, Bhi + gb);
            cp16(st + 3 * G_ARR + so, Blo + gb);
        }
        CP_COMMIT();
    }

    for (int s = 0; s < DMODEL / 32; ++s) {
        CP_WAIT_ALL();
        __syncthreads();

        if (s + 1 < DMODEL / 32) {
            const int kofs = (s + 1) * 32;
            const uint32_t st = smb + ((s + 1) & 1) * G_STAGE;
#pragma unroll
            for (int it = 0; it < 2; ++it) {
                const int row = it ? row1 : row0;
                const int c8  = it ? c81 : c80;
                const size_t ga = (arow0 + row) * DMODEL + kofs + c8;
                const size_t gb = (brow0 + row) * DMODEL + kofs + c8;
                const uint32_t so = (row * LDSB + c8) * 2;
                cp16(st + so,             Ahi + ga);
                cp16(st + G_ARR + so,     Alo + ga);
                cp16(st + 2 * G_ARR + so, Bhi + gb);
                cp16(st + 3 * G_ARR + so, Blo + gb);
            }
            CP_COMMIT();
        }

        const uint32_t sAhi_u = smb + (s & 1) * G_STAGE;
        const uint32_t sAlo_u = sAhi_u + G_ARR;
        const uint32_t sBhi_u = sAhi_u + 2 * G_ARR;
        const uint32_t sBlo_u = sAhi_u + 3 * G_ARR;

#pragma unroll
        for (int kk = 0; kk < 2; ++kk) {
            const int kc = kk * 16;
            uint32_t bh[4][2], bl[4][2];
#pragma unroll
            for (int p = 0; p < 2; ++p) {
                uint32_t r[4];
                uint32_t boff = ((warp_n + p * 16 + b_row) * LDSB + kc + b_ksel) * 2;
                ldm_x4(sBhi_u + boff, r);
                bh[p * 2 + 0][0] = r[0]; bh[p * 2 + 0][1] = r[1];
                bh[p * 2 + 1][0] = r[2]; bh[p * 2 + 1][1] = r[3];
                ldm_x4(sBlo_u + boff, r);
                bl[p * 2 + 0][0] = r[0]; bl[p * 2 + 0][1] = r[1];
                bl[p * 2 + 1][0] = r[2]; bl[p * 2 + 1][1] = r[3];
            }
#pragma unroll
            for (int mt = 0; mt < 4; ++mt) {
                uint32_t aoff = ((warp_m + mt * 16 + a_row) * LDSB + kc + a_ksel) * 2;
                uint32_t ah[4], al[4];
                ldm_x4(sAhi_u + aoff, ah);
                ldm_x4(sAlo_u + aoff, al);
#pragma unroll
                for (int nt = 0; nt < 4; ++nt) {
                    mma_bf16(acc[mt][nt], ah, bh[nt][0], bh[nt][1]);
                    mma_bf16(acc[mt][nt], ah, bl[nt][0], bl[nt][1]);
                    mma_bf16(acc[mt][nt], al, bh[nt][0], bh[nt][1]);
                }
            }
        }
        __syncthreads();
    }

    const int gq = lane >> 2;
    const int cq = (lane & 3) * 2;
#pragma unroll
    for (int mt = 0; mt < 4; ++mt) {
        const int r_lo = bm * 128 + warp_m + mt * 16 + gq;
#pragma unroll
        for (int nt = 0; nt < 4; ++nt) {
            const int c = bn * 128 + warp_n + nt * 8 + cq;
            const float b0 = bias[c], b1 = bias[c + 1];
            float v0 = acc[mt][nt][0] + b0, v1 = acc[mt][nt][1] + b1;
            float v2 = acc[mt][nt][2] + b0, v3 = acc[mt][nt][3] + b1;
            if (SPLIT) {
                uint32_t h0, l0, h1, l1;
                split_pack(v0, v1, h0, l0);
                split_pack(v2, v3, h1, l1);
                *(uint32_t*)(Chi + (size_t)r_lo * DMODEL + c) = h0;
                *(uint32_t*)(Clo + (size_t)r_lo * DMODEL + c) = l0;
                *(uint32_t*)(Chi + (size_t)(r_lo + 8) * DMODEL + c) = h1;
                *(uint32_t*)(Clo + (size_t)(r_lo + 8) * DMODEL + c) = l1;
            } else {
                *(float2*)(C + (size_t)r_lo * DMODEL + c) = make_float2(v0, v1);
                *(float2*)(C + (size_t)(r_lo + 8) * DMODEL + c) = make_float2(v2, v3);
            }
        }
    }
}

__global__ __launch_bounds__(256, 2)
void gemm_qkv_hmma(const float* __restrict__ bq, const float* __restrict__ bk,
                   const float* __restrict__ bv)
{
    const int z = blockIdx.z;
    const float* bias = (z == 0) ? bq : (z == 1) ? bk : bv;
    __nv_bfloat16* Chi = (z == 0) ? g_qhi : (z == 1) ? g_khi : g_vhi;
    __nv_bfloat16* Clo = (z == 0) ? g_qlo : (z == 1) ? g_klo : g_vlo;
    hmma_gemm_body<true>(g_xhi, g_xlo, g_whi[z], g_wlo[z], bias,
                         nullptr, Chi, Clo, blockIdx.y, blockIdx.x);
}

__global__ __launch_bounds__(256, 2)
void gemm_out_hmma(const float* __restrict__ bo, float* __restrict__ out)
{
    hmma_gemm_body<false>(g_ahi, g_alo, g_whi[3], g_wlo[3], bo,
                          out, nullptr, nullptr, blockIdx.y, blockIdx.x);
}

// ---------------------------------------------------------------------------
// HMMA flash attention, split-bf16 3-term, cp.async double-buffered K/V,
// V row-major + ldmatrix.trans for PV (no scalar transpose stores).
// Block: 128 threads = 4 warps, 64 q-rows. KV tiles of 64.
// Dyn smem: QH|QL (9216 each) + 2 stages x (KH|KL|VH|VL) + bias.
// ---------------------------------------------------------------------------
#define ALDS 72
#define A_QH    0
#define A_QL    9216
#define A_ST0   18432
#define A_SSTR  36864
#define ST_KH   0
#define ST_KL   9216
#define ST_VH   18432
#define ST_VL   27648
#define A_BIAS  92160
#define A_TOTAL 92416

__global__ __launch_bounds__(128)
void attn_hmma(const unsigned char* __restrict__ mask)
{
    extern __shared__ char smem[];
    float* sbias = (float*)(smem + A_BIAS);

    const int tid  = threadIdx.x;
    const int wid  = tid >> 5;
    const int lane = tid & 31;

    const int qt = (int)gridDim.x - 1 - (int)blockIdx.x;  // big tiles first
    const int bh = blockIdx.y;
    const int b  = bh >> 4;
    const int h  = bh & 15;
    const int q0 = qt * 64;

    const size_t qbase = (size_t)(b * SEQ + q0) * DMODEL + h * DHEAD;
    const unsigned char* mb = mask + (size_t)b * SEQ;
    const uint32_t smb = smem_u32(smem);

    // per-thread K/V load coords (4 chunks of uint4)
    const int lrow[4] = { tid >> 3, (tid + 128) >> 3, (tid + 256) >> 3, (tid + 384) >> 3 };
    const int lc8 = (tid & 7) * 8;

    // ---- load Q tile (hi/lo) + prefetch KV tile 0 ----
#pragma unroll
    for (int it = 0; it < 4; ++it) {
        const int row = lrow[it];
        *(uint4*)(smem + A_QH + (row * ALDS + lc8) * 2) =
            *(const uint4*)(g_qhi + qbase + (size_t)row * DMODEL + lc8);
        *(uint4*)(smem + A_QL + (row * ALDS + lc8) * 2) =
            *(const uint4*)(g_qlo + qbase + (size_t)row * DMODEL + lc8);
    }
    {
        const size_t kvb = (size_t)(b * SEQ) * DMODEL + h * DHEAD;   // tile 0
        const uint32_t st = smb + A_ST0;
#pragma unroll
        for (int it = 0; it < 4; ++it) {
            const int row = lrow[it];
            const size_t g = kvb + (size_t)row * DMODEL + lc8;
            const uint32_t so = (row * ALDS + lc8) * 2;
            cp16(st + ST_KH + so, g_khi + g);
            cp16(st + ST_KL + so, g_klo + g);
            cp16(st + ST_VH + so, g_vhi + g);
            cp16(st + ST_VL + so, g_vlo + g);
        }
        CP_COMMIT();
    }
    __syncthreads();

    // ---- preload Q fragments ----
    const int a_row  = lane & 15;
    const int a_ksel = (lane >> 4) * 8;
    const int b_row  = (lane & 7) + ((lane >> 4) & 1) * 8;
    const int b_ksel = ((lane >> 3) & 1) * 8;

    uint32_t qh[4][4], ql[4][4];
#pragma unroll
    for (int kk = 0; kk < 4; ++kk) {
        const uint32_t off = ((wid * 16 + a_row) * ALDS + kk * 16 + a_ksel) * 2;
        ldm_x4(smb + A_QH + off, qh[kk]);
        ldm_x4(smb + A_QL + off, ql[kk]);
    }

    float mA = -1e30f, mB = -1e30f, lA = 0.f, lB = 0.f;
    float o[8][4];
#pragma unroll
    for (int nt = 0; nt < 8; ++nt)
#pragma unroll
        for (int t = 0; t < 4; ++t) o[nt][t] = 0.f;

    const int rowA = q0 + wid * 16 + (lane >> 2);
    const int rowB = rowA + 8;
    const float SC = 0.125f * 1.44269504f;

    for (int j = 0; j <= qt; ++j) {
        CP_WAIT_ALL();
        __syncthreads();            // stage j data visible; prior compute done

        if (tid < 64)
            sbias[tid] = mb[j * 64 + tid] ? -1e30f : 0.f;

        if (j < qt) {               // prefetch tile j+1 into the other stage
            const size_t kvb = (size_t)(b * SEQ + (j + 1) * 64) * DMODEL + h * DHEAD;
            const uint32_t st = smb + A_ST0 + ((j + 1) & 1) * A_SSTR;
#pragma unroll
            for (int it = 0; it < 4; ++it) {
                const int row = lrow[it];
                const size_t g = kvb + (size_t)row * DMODEL + lc8;
                const uint32_t so = (row * ALDS + lc8) * 2;
                cp16(st + ST_KH + so, g_khi + g);
                cp16(st + ST_KL + so, g_klo + g);
                cp16(st + ST_VH + so, g_vhi + g);
                cp16(st + ST_VL + so, g_vlo + g);
            }
            CP_COMMIT();
        }
        __syncthreads();            // sbias visible

        const uint32_t stg = smb + A_ST0 + (j & 1) * A_SSTR;
        const uint32_t sKH = stg + ST_KH;
        const uint32_t sKL = stg + ST_KL;
        const uint32_t sVH = stg + ST_VH;
        const uint32_t sVL = stg + ST_VL;

        // ---- S = Q K^T (3-term) ----
        float s[8][4];
#pragma unroll
        for (int nt = 0; nt < 8; ++nt)
#pragma unroll
            for (int t = 0; t < 4; ++t) s[nt][t] = 0.f;

#pragma unroll
        for (int kk = 0; kk < 4; ++kk) {
            const int kc = kk * 16;
#pragma unroll
            for (int p = 0; p < 4; ++p) {
                uint32_t bh4[4], bl4[4];
                const uint32_t boff = ((p * 16 + b_row) * ALDS + kc + b_ksel) * 2;
                ldm_x4(sKH + boff, bh4);
                ldm_x4(sKL + boff, bl4);
                mma_bf16(s[2 * p],     qh[kk], bh4[0], bh4[1]);
                mma_bf16(s[2 * p + 1], qh[kk], bh4[2], bh4[3]);
                mma_bf16(s[2 * p],     qh[kk], bl4[0], bl4[1]);
                mma_bf16(s[2 * p + 1], qh[kk], bl4[2], bl4[3]);
                mma_bf16(s[2 * p],     ql[kk], bh4[0], bh4[1]);
                mma_bf16(s[2 * p + 1], ql[kk], bh4[2], bh4[3]);
            }
        }

        // ---- scale + padding bias + causal (diag tile only) ----
        const bool diag = (j == qt);
#pragma unroll
        for (int nt = 0; nt < 8; ++nt) {
            const float2 bia = *(const float2*)&sbias[nt * 8 + (lane & 3) * 2];
            s[nt][0] = s[nt][0] * SC + bia.x;
            s[nt][1] = s[nt][1] * SC + bia.y;
            s[nt][2] = s[nt][2] * SC + bia.x;
            s[nt][3] = s[nt][3] * SC + bia.y;
            if (diag) {
                const int c0g = j * 64 + nt * 8 + (lane & 3) * 2;
                if (c0g     > rowA) s[nt][0] = -1e30f;
                if (c0g + 1 > rowA) s[nt][1] = -1e30f;
                if (c0g     > rowB) s[nt][2] = -1e30f;
                if (c0g + 1 > rowB) s[nt][3] = -1e30f;
            }
        }

        // ---- online softmax ----
        float tmA = -1e30f, tmB = -1e30f;
#pragma unroll
        for (int nt = 0; nt < 8; ++nt) {
            tmA = fmaxf(tmA, fmaxf(s[nt][0], s[nt][1]));
            tmB = fmaxf(tmB, fmaxf(s[nt][2], s[nt][3]));
        }
        tmA = fmaxf(tmA, __shfl_xor_sync(0xffffffffu, tmA, 1));
        tmA = fmaxf(tmA, __shfl_xor_sync(0xffffffffu, tmA, 2));
        tmB = fmaxf(tmB, __shfl_xor_sync(0xffffffffu, tmB, 1));
        tmB = fmaxf(tmB, __shfl_xor_sync(0xffffffffu, tmB, 2));

        const float mnA = fmaxf(mA, tmA);
        const float mnB = fmaxf(mB, tmB);
        const float alA = exp2f(mA - mnA);
        const float alB = exp2f(mB - mnB);
        mA = mnA; mB = mnB;

        float psA = 0.f, psB = 0.f;
#pragma unroll
        for (int nt = 0; nt < 8; ++nt) {
            s[nt][0] = exp2f(s[nt][0] - mA);
            s[nt][1] = exp2f(s[nt][1] - mA);
            s[nt][2] = exp2f(s[nt][2] - mB);
            s[nt][3] = exp2f(s[nt][3] - mB);
            psA += s[nt][0] + s[nt][1];
            psB += s[nt][2] + s[nt][3];
        }
        psA += __shfl_xor_sync(0xffffffffu, psA, 1);
        psA += __shfl_xor_sync(0xffffffffu, psA, 2);
        psB += __shfl_xor_sync(0xffffffffu, psB, 1);
        psB += __shfl_xor_sync(0xffffffffu, psB, 2);
        lA = lA * alA + psA;
        lB = lB * alB + psB;

#pragma unroll
        for (int nt = 0; nt < 8; ++nt) {
            o[nt][0] *= alA; o[nt][1] *= alA;
            o[nt][2] *= alB; o[nt][3] *= alB;
        }

        // ---- O += P V  (P split from regs; V row-major via ldmatrix.trans) ----
#pragma unroll
        for (int t = 0; t < 4; ++t) {
            uint32_t ah4[4], al4[4];
            split_pack(s[2 * t][0],     s[2 * t][1],     ah4[0], al4[0]);
            split_pack(s[2 * t][2],     s[2 * t][3],     ah4[1], al4[1]);
            split_pack(s[2 * t + 1][0], s[2 * t + 1][1], ah4[2], al4[2]);
            split_pack(s[2 * t + 1][2], s[2 * t + 1][3], ah4[3], al4[3]);
#pragma unroll
            for (int p = 0; p < 4; ++p) {
                uint32_t vh4[4], vl4[4];
                // V[kv][dh]: rows t*16+(lane&15), col group p*16 + (lane>>4)*8
                const uint32_t voff =
                    ((t * 16 + (lane & 15)) * ALDS + p * 16 + (lane >> 4) * 8) * 2;
                ldm_x4_trans(sVH + voff, vh4);
                ldm_x4_trans(sVL + voff, vl4);
                mma_bf16(o[2 * p],     ah4, vh4[0], vh4[1]);
                mma_bf16(o[2 * p + 1], ah4, vh4[2], vh4[3]);
                mma_bf16(o[2 * p],     ah4, vl4[0], vl4[1]);
                mma_bf16(o[2 * p + 1], ah4, vl4[2], vl4[3]);
                mma_bf16(o[2 * p],     al4, vh4[0], vh4[1]);
                mma_bf16(o[2 * p + 1], al4, vh4[2], vh4[3]);
            }
        }
    }

    // ---- epilogue: normalize, split to bf16 hi/lo for out-projection ----
    const float invA = 1.0f / lA;
    const float invB = 1.0f / lB;
    const size_t grA = (size_t)(b * SEQ + rowA) * DMODEL;
    const size_t grB = (size_t)(b * SEQ + rowB) * DMODEL;
#pragma unroll
    for (int nt = 0; nt < 8; ++nt) {
        const int col = h * DHEAD + nt * 8 + (lane & 3) * 2;
        uint32_t h0, l0, h1, l1;
        split_pack(o[nt][0] * invA, o[nt][1] * invA, h0, l0);
        split_pack(o[nt][2] * invB, o[nt][3] * invB, h1, l1);
        *(uint32_t*)(g_ahi + grA + col) = h0;
        *(uint32_t*)(g_alo + grA + col) = l0;
        *(uint32_t*)(g_ahi + grB + col) = h1;
        *(uint32_t*)(g_alo + grB + col) = l1;
    }
}

// ---------------------------------------------------------------------------
extern "C" void kernel_launch(void* const* d_in, const int* in_sizes, int n_in,
                              void* d_out, int out_size)
{
    const float*         x    = (const float*)d_in[0];
    const unsigned char* mask = (const unsigned char*)d_in[1];
    const float*         wq   = (const float*)d_in[2];
    const float*         bq   = (const float*)d_in[3];
    const float*         wk   = (const float*)d_in[4];
    const float*         bk   = (const float*)d_in[5];
    const float*         wv   = (const float*)d_in[6];
    const float*         bv   = (const float*)d_in[7];
    const float*         wo   = (const float*)d_in[8];
    const float*         bo   = (const float*)d_in[9];
    float*               out  = (float*)d_out;

    cudaFuncSetAttribute(attn_hmma,
                         cudaFuncAttributeMaxDynamicSharedMemorySize, A_TOTAL);
    cudaFuncSetAttribute(gemm_qkv_hmma,
                         cudaFuncAttributeMaxDynamicSharedMemorySize, G_TOTAL);
    cudaFuncSetAttribute(gemm_out_hmma,
                         cudaFuncAttributeMaxDynamicSharedMemorySize, G_TOTAL);

    // split inputs to bf16 hi/lo
    split_x_kernel<<<MROWS * DMODEL / 4 / 256, 256>>>(x);
    split_w_kernel<<<dim3(DMODEL * DMODEL / 4 / 256, 4), 256>>>(wq, wk, wv, wo);

    // QKV projections on HMMA (write split bf16 directly)
    gemm_qkv_hmma<<<dim3(DMODEL / 128, MROWS / 128, 3), 256, G_TOTAL>>>(bq, bk, bv);

    // flash attention on HMMA (writes split bf16 directly)
    attn_hmma<<<dim3(SEQ / 64, BATCH * NHEADS), 128, A_TOTAL>>>(mask);

    // output projection on HMMA
    gemm_out_hmma<<<dim3(DMODEL / 128, MROWS / 128), 256, G_TOTAL>>>(bo, out);
}